// round 16
// baseline (speedup 1.0000x reference)
#include <cuda_runtime.h>
#include <math.h>

#define BATCH 16
#define NPTS  4096

// ---------- device scratch (16B-aligned for float4 access) ----------
__device__ __align__(16) float g_l1x[BATCH*512*3];
__device__ __align__(16) int   g_bq1[BATCH*512*32];
__device__ __align__(16) float g_l1f[BATCH*512*128];
__device__ __align__(16) float g_l2x[BATCH*128*3];
__device__ __align__(16) int   g_bq2[BATCH*128*64];
__device__ __align__(16) float g_l2f[BATCH*128*256];
__device__ __align__(16) float g_y1 [2048*256];
__device__ __align__(16) float g_y2 [2048*512];
__device__ __align__(16) float g_y3 [2048*1024];
__device__ __align__(16) float g_g  [BATCH*1024];
__device__ __align__(16) float g_hl [BATCH*256];
__device__ __align__(16) float g_hf [BATCH*512];
__device__ __align__(16) float g_ha [16777216];   // 64MB
__device__ __align__(16) float g_hb [16777216];   // 64MB
__device__ __align__(16) float g_hc [33554432];   // 128MB

// squared distance, exactly as XLA lowers sum((a-b)**2, -1)
__device__ __forceinline__ float dist2(float dx, float dy, float dz)
{
    return __fadd_rn(__fadd_rn(__fmul_rn(dx,dx), __fmul_rn(dy,dy)), __fmul_rn(dz,dz));
}

// ---------- farthest point sampling (register-resident) ----------
template<int N, int NP>
__device__ __forceinline__ void fps_body(const float* __restrict__ xyz,
                                         float* __restrict__ newxyz)
{
    constexpr int TPB = 256, NPER = N / TPB;
    __shared__ float rv[8];
    __shared__ int   ri[8];
    __shared__ int   s_far;
    __shared__ float sfx, sfy, sfz;
    const int b = blockIdx.x, t = threadIdx.x;
    const float* p = xyz + (size_t)b * N * 3;

    float lx[NPER], ly[NPER], lz[NPER], ld[NPER];
#pragma unroll
    for (int u = 0; u < NPER; u++) {
        int j = t + u*TPB;
        lx[u]=p[j*3]; ly[u]=p[j*3+1]; lz[u]=p[j*3+2]; ld[u]=1e10f;
    }
    if (t == 0) { sfx = lx[0]; sfy = ly[0]; sfz = lz[0]; }
    __syncthreads();

    for (int i = 0; i < NP; i++) {
        float fx = sfx, fy = sfy, fz = sfz;
        if (t == 0) {
            newxyz[((size_t)b*NP+i)*3+0]=fx;
            newxyz[((size_t)b*NP+i)*3+1]=fy;
            newxyz[((size_t)b*NP+i)*3+2]=fz;
        }
        float bv = -1.f; int bi = 0x7fffffff;
#pragma unroll
        for (int u = 0; u < NPER; u++) {
            float d  = dist2(lx[u]-fx, ly[u]-fy, lz[u]-fz);
            float nd = fminf(ld[u], d);
            ld[u] = nd;
            if (nd > bv) { bv = nd; bi = t + u*TPB; }
        }
#pragma unroll
        for (int off = 16; off; off >>= 1) {
            float ov = __shfl_down_sync(0xffffffffu, bv, off);
            int   oi = __shfl_down_sync(0xffffffffu, bi, off);
            if (ov > bv || (ov == bv && oi < bi)) { bv = ov; bi = oi; }
        }
        if ((t & 31) == 0) { rv[t>>5]=bv; ri[t>>5]=bi; }
        __syncthreads();
        if (t == 0) {
#pragma unroll
            for (int q = 1; q < 8; q++)
                if (rv[q] > bv || (rv[q] == bv && ri[q] < bi)) { bv=rv[q]; bi=ri[q]; }
            s_far = bi;
        }
        __syncthreads();
        int far = s_far;
        if (t == (far & (TPB-1))) {
            int u = far / TPB;
            sfx = lx[u]; sfy = ly[u]; sfz = lz[u];
        }
        __syncthreads();
    }
}
__global__ __launch_bounds__(256) void fps1_kernel(const float* __restrict__ pts)
{ fps_body<NPTS,512>(pts, g_l1x); }
__global__ __launch_bounds__(256) void fps2_kernel()
{ fps_body<512,128>(g_l1x, g_l2x); }

// ---------- ball query (warp per center) ----------
template<int NSRC, int NS>
__device__ __forceinline__ void bq_body(const float* __restrict__ xyz,
                                        const float* __restrict__ newxyz,
                                        int S, float r2, int* __restrict__ out)
{
    __shared__ int buf[4][NS];
    const int w = (blockIdx.x*blockDim.x + threadIdx.x) >> 5;
    const int lane = threadIdx.x & 31, wl = threadIdx.x >> 5;
    const int b = w / S;
    const float* p = xyz + (size_t)b * NSRC * 3;
    const float cx=newxyz[(size_t)w*3], cy=newxyz[(size_t)w*3+1], cz=newxyz[(size_t)w*3+2];
    int count = 0;
    for (int j0 = 0; j0 < NSRC && count < NS; j0 += 32) {
        int j = j0 + lane;
        float d = dist2(cx-p[j*3], cy-p[j*3+1], cz-p[j*3+2]);
        bool in = !(d > r2);
        unsigned m = __ballot_sync(0xffffffffu, in);
        int pos = count + __popc(m & ((1u<<lane)-1u));
        if (in && pos < NS) buf[wl][pos] = j;
        count += __popc(m);
    }
    __syncwarp();
    if (count > NS) count = NS;
    int first = buf[wl][0];
    for (int k = lane; k < NS; k += 32)
        out[(size_t)w*NS + k] = (k < count) ? buf[wl][k] : first;
}
__global__ __launch_bounds__(128) void bq1_kernel(const float* __restrict__ pts)
{ bq_body<NPTS,32>(pts, g_l1x, 512, (float)(0.2*0.2), g_bq1); }
__global__ __launch_bounds__(128) void bq2_kernel()
{ bq_body<512,64>(g_l1x, g_l2x, 128, (float)(0.4*0.4), g_bq2); }

// ================= 8x8 register-microtiled GEMM body =================
// Y[r,o] = relu(bias[o] + sum_k X[r,k] W[k,o]); 8 rows x 8 outs per thread.
// k-ascending accumulation per output (matches reference numerics).
template<int CIN, int COUT>
__device__ __forceinline__ void gemm_body8(const float* __restrict__ X,
    const float* __restrict__ W, const float* __restrict__ Bv,
    float* __restrict__ Y)
{
    constexpr int TPR = COUT/8;        // threads covering one row-group
    constexpr int RPB = (256/TPR)*8;   // rows per block
    const int t = threadIdx.x;
    const int o0 = (t % TPR)*8;
    const int r0 = blockIdx.x*RPB + (t/TPR)*8;
    const float* x0 = X + (size_t)r0*CIN;
    float4 b0 = *reinterpret_cast<const float4*>(Bv + o0);
    float4 b1 = *reinterpret_cast<const float4*>(Bv + o0 + 4);
    float acc[8][8];
#pragma unroll
    for (int i = 0; i < 8; i++) {
        acc[i][0]=b0.x; acc[i][1]=b0.y; acc[i][2]=b0.z; acc[i][3]=b0.w;
        acc[i][4]=b1.x; acc[i][5]=b1.y; acc[i][6]=b1.z; acc[i][7]=b1.w;
    }
#pragma unroll 1
    for (int k = 0; k < CIN; k += 4) {
        float a[8][4];
#pragma unroll
        for (int i = 0; i < 8; i++) {
            float4 v = *reinterpret_cast<const float4*>(x0 + (size_t)i*CIN + k);
            a[i][0]=v.x; a[i][1]=v.y; a[i][2]=v.z; a[i][3]=v.w;
        }
#pragma unroll
        for (int kk = 0; kk < 4; kk++) {
            const float* wp = W + (size_t)(k+kk)*COUT + o0;
            float4 w0 = *reinterpret_cast<const float4*>(wp);
            float4 w1 = *reinterpret_cast<const float4*>(wp + 4);
#pragma unroll
            for (int i = 0; i < 8; i++) {
                float av = a[i][kk];
                acc[i][0] += av*w0.x; acc[i][1] += av*w0.y;
                acc[i][2] += av*w0.z; acc[i][3] += av*w0.w;
                acc[i][4] += av*w1.x; acc[i][5] += av*w1.y;
                acc[i][6] += av*w1.z; acc[i][7] += av*w1.w;
            }
        }
    }
#pragma unroll
    for (int i = 0; i < 8; i++) {
        float* yp = Y + (size_t)(r0+i)*COUT + o0;
#pragma unroll
        for (int j = 0; j < 8; j++) yp[j] = fmaxf(acc[i][j], 0.f);
    }
}

// per-layer wrappers (device globals named in device code only)
__global__ __launch_bounds__(256) void k_sa1_l2(const float* __restrict__ W, const float* __restrict__ B)
{ gemm_body8<64,64>(g_ha, W, B, g_hb); }
__global__ __launch_bounds__(256) void k_sa1_l3(const float* __restrict__ W, const float* __restrict__ B)
{ gemm_body8<64,128>(g_hb, W, B, g_hc); }
__global__ __launch_bounds__(256) void k_sa2_l2(const float* __restrict__ W, const float* __restrict__ B)
{ gemm_body8<128,128>(g_ha, W, B, g_hb); }
__global__ __launch_bounds__(256) void k_sa2_l3(const float* __restrict__ W, const float* __restrict__ B)
{ gemm_body8<128,256>(g_hb, W, B, g_hc); }
__global__ __launch_bounds__(256) void k_sa3_l2(const float* __restrict__ W, const float* __restrict__ B)
{ gemm_body8<256,512>(g_y1, W, B, g_y2); }
__global__ __launch_bounds__(256) void k_sa3_l3(const float* __restrict__ W, const float* __restrict__ B)
{ gemm_body8<512,1024>(g_y2, W, B, g_y3); }

// SA1 layer1 (3 -> 64), thread-per-output (tiny compute, memory bound)
__global__ void d_sa1_l1(const float* __restrict__ points,
                         const float* __restrict__ w, const float* __restrict__ bv)
{
    int i = blockIdx.x*blockDim.x + threadIdx.x;   // 8192*32*64
    int o = i & 63, r = (i>>6) & 31, g = i >> 11, b = g >> 9;
    int id = g_bq1[(size_t)g*32 + r];
    float acc = bv[o];
    for (int c = 0; c < 3; c++) {
        float x = points[((size_t)(b*NPTS)+id)*3 + c] - g_l1x[(size_t)g*3 + c];
        acc += x * w[c*64 + o];
    }
    g_ha[i] = fmaxf(acc, 0.f);
}
__global__ void d_sa1_pool()
{
    int i = blockIdx.x*blockDim.x + threadIdx.x;   // 8192*128
    int o = i & 127, g = i >> 7;
    float m = -1e30f;
    for (int r = 0; r < 32; r++)
        m = fmaxf(m, g_hc[((size_t)(g*32+r))*128 + o]);
    g_l1f[i] = m;
}

// SA2 layer1: gather + concat(xyz diff, 128 feats) -> 128, 8x8 microtiled
__global__ __launch_bounds__(256) void gemm_sa2l1(const float* __restrict__ W,
                                                  const float* __restrict__ Bv)
{
    constexpr int COUT = 128, TPR = COUT/8;   // 16
    constexpr int RPB = (256/TPR)*8;          // 128 rows/block
    const int t = threadIdx.x;
    const int o0 = (t % TPR)*8;
    const int r0 = blockIdx.x*RPB + (t/TPR)*8;  // rows: 131072
    float4 b0 = *reinterpret_cast<const float4*>(Bv + o0);
    float4 b1 = *reinterpret_cast<const float4*>(Bv + o0 + 4);
    const float* fp[8];
    float acc[8][8];
#pragma unroll
    for (int i = 0; i < 8; i++) {
        int r = r0 + i, g = r >> 6, rr = r & 63, b = g >> 7;
        int id = g_bq2[(size_t)g*64 + rr];
        float dx = g_l1x[(size_t)(b*512+id)*3+0] - g_l2x[(size_t)g*3+0];
        float dy = g_l1x[(size_t)(b*512+id)*3+1] - g_l2x[(size_t)g*3+1];
        float dz = g_l1x[(size_t)(b*512+id)*3+2] - g_l2x[(size_t)g*3+2];
        const float* w0 = W + o0;
        const float* w1 = W + COUT + o0;
        const float* w2 = W + 2*COUT + o0;
        acc[i][0]=b0.x+dx*w0[0]+dy*w1[0]+dz*w2[0];
        acc[i][1]=b0.y+dx*w0[1]+dy*w1[1]+dz*w2[1];
        acc[i][2]=b0.z+dx*w0[2]+dy*w1[2]+dz*w2[2];
        acc[i][3]=b0.w+dx*w0[3]+dy*w1[3]+dz*w2[3];
        acc[i][4]=b1.x+dx*w0[4]+dy*w1[4]+dz*w2[4];
        acc[i][5]=b1.y+dx*w0[5]+dy*w1[5]+dz*w2[5];
        acc[i][6]=b1.z+dx*w0[6]+dy*w1[6]+dz*w2[6];
        acc[i][7]=b1.w+dx*w0[7]+dy*w1[7]+dz*w2[7];
        fp[i] = g_l1f + (size_t)(b*512+id)*128;
    }
#pragma unroll 1
    for (int k = 0; k < 128; k += 4) {
        float a[8][4];
#pragma unroll
        for (int i = 0; i < 8; i++) {
            float4 v = *reinterpret_cast<const float4*>(fp[i] + k);
            a[i][0]=v.x; a[i][1]=v.y; a[i][2]=v.z; a[i][3]=v.w;
        }
#pragma unroll
        for (int kk = 0; kk < 4; kk++) {
            const float* wp = W + (size_t)(3+k+kk)*COUT + o0;
            float4 w0 = *reinterpret_cast<const float4*>(wp);
            float4 w1 = *reinterpret_cast<const float4*>(wp + 4);
#pragma unroll
            for (int i = 0; i < 8; i++) {
                float av = a[i][kk];
                acc[i][0] += av*w0.x; acc[i][1] += av*w0.y;
                acc[i][2] += av*w0.z; acc[i][3] += av*w0.w;
                acc[i][4] += av*w1.x; acc[i][5] += av*w1.y;
                acc[i][6] += av*w1.z; acc[i][7] += av*w1.w;
            }
        }
    }
#pragma unroll
    for (int i = 0; i < 8; i++) {
        float* yp = g_ha + (size_t)(r0+i)*COUT + o0;
#pragma unroll
        for (int j = 0; j < 8; j++) yp[j] = fmaxf(acc[i][j], 0.f);
    }
}
__global__ void d_sa2_pool()
{
    int i = blockIdx.x*blockDim.x + threadIdx.x;   // 2048*256
    int o = i & 255, g = i >> 8;
    float m = -1e30f;
    for (int r = 0; r < 64; r++)
        m = fmaxf(m, g_hc[((size_t)(g*64+r))*256 + o]);
    g_l2f[i] = m;
}

// SA3 layer1: concat(l2x, l2f) (3+256) -> 256, 8x8 microtiled; rows = 2048
__global__ __launch_bounds__(256) void gemm_sa3l1(const float* __restrict__ W,
                                                  const float* __restrict__ Bv)
{
    constexpr int COUT = 256, TPR = COUT/8;   // 32
    constexpr int RPB = (256/TPR)*8;          // 64 rows/block
    const int t = threadIdx.x;
    const int o0 = (t % TPR)*8;
    const int r0 = blockIdx.x*RPB + (t/TPR)*8;
    float4 b0 = *reinterpret_cast<const float4*>(Bv + o0);
    float4 b1 = *reinterpret_cast<const float4*>(Bv + o0 + 4);
    float acc[8][8];
#pragma unroll
    for (int i = 0; i < 8; i++) {
        int r = r0 + i;
        float x = g_l2x[(size_t)r*3+0], y = g_l2x[(size_t)r*3+1], z = g_l2x[(size_t)r*3+2];
        const float* w0 = W + o0;
        const float* w1 = W + COUT + o0;
        const float* w2 = W + 2*COUT + o0;
        acc[i][0]=b0.x+x*w0[0]+y*w1[0]+z*w2[0];
        acc[i][1]=b0.y+x*w0[1]+y*w1[1]+z*w2[1];
        acc[i][2]=b0.z+x*w0[2]+y*w1[2]+z*w2[2];
        acc[i][3]=b0.w+x*w0[3]+y*w1[3]+z*w2[3];
        acc[i][4]=b1.x+x*w0[4]+y*w1[4]+z*w2[4];
        acc[i][5]=b1.y+x*w0[5]+y*w1[5]+z*w2[5];
        acc[i][6]=b1.z+x*w0[6]+y*w1[6]+z*w2[6];
        acc[i][7]=b1.w+x*w0[7]+y*w1[7]+z*w2[7];
    }
    const float* x0 = g_l2f + (size_t)r0*256;
#pragma unroll 1
    for (int k = 0; k < 256; k += 4) {
        float a[8][4];
#pragma unroll
        for (int i = 0; i < 8; i++) {
            float4 v = *reinterpret_cast<const float4*>(x0 + (size_t)i*256 + k);
            a[i][0]=v.x; a[i][1]=v.y; a[i][2]=v.z; a[i][3]=v.w;
        }
#pragma unroll
        for (int kk = 0; kk < 4; kk++) {
            const float* wp = W + (size_t)(3+k+kk)*COUT + o0;
            float4 w0 = *reinterpret_cast<const float4*>(wp);
            float4 w1 = *reinterpret_cast<const float4*>(wp + 4);
#pragma unroll
            for (int i = 0; i < 8; i++) {
                float av = a[i][kk];
                acc[i][0] += av*w0.x; acc[i][1] += av*w0.y;
                acc[i][2] += av*w0.z; acc[i][3] += av*w0.w;
                acc[i][4] += av*w1.x; acc[i][5] += av*w1.y;
                acc[i][6] += av*w1.z; acc[i][7] += av*w1.w;
            }
        }
    }
#pragma unroll
    for (int i = 0; i < 8; i++) {
        float* yp = g_y1 + (size_t)(r0+i)*COUT + o0;
#pragma unroll
        for (int j = 0; j < 8; j++) yp[j] = fmaxf(acc[i][j], 0.f);
    }
}
__global__ void d_pool3()
{
    int i = blockIdx.x*blockDim.x + threadIdx.x;   // 16*1024
    int b = i >> 10, c = i & 1023;
    float m = -1e30f;
    for (int r = 0; r < 128; r++)
        m = fmaxf(m, g_y3[(size_t)((b*128+r)<<10) + c]);
    g_g[i] = m;
}
// heads
__global__ void d_head1(const float* __restrict__ lw1, const float* __restrict__ lb1,
                        const float* __restrict__ fw1, const float* __restrict__ fb1)
{
    int i = blockIdx.x*blockDim.x + threadIdx.x;   // 16*768
    if (i >= 16*768) return;
    int b = i / 768, o = i % 768;
    if (o < 256) {
        float s = lb1[o];
        for (int k = 0; k < 1024; k++) s += g_g[(size_t)b*1024+k] * lw1[(size_t)k*256 + o];
        g_hl[b*256+o] = fmaxf(s, 0.f);
    } else {
        int o2 = o - 256;
        float s = fb1[o2];
        for (int k = 0; k < 1024; k++) s += g_g[(size_t)b*1024+k] * fw1[(size_t)k*512 + o2];
        g_hf[b*512+o2] = fmaxf(s, 0.f);
    }
}
__global__ void d_head2(const float* __restrict__ lw2, const float* __restrict__ lb2,
                        const float* __restrict__ fw2, const float* __restrict__ fb2,
                        const float* __restrict__ pos_mean, const float* __restrict__ pos_std,
                        const float* __restrict__ rot_mean, const float* __restrict__ rot_std,
                        float* __restrict__ out)
{
    int i = threadIdx.x;
    if (i >= 320) return;
    int b = i / 20, c = i % 20;
    float v;
    if (c < 2) {
        float s = lb2[c];
        for (int k = 0; k < 256; k++) s += g_hl[b*256+k] * lw2[k*2+c];
        v = 1.f/(1.f + expf(-s));
    } else {
        int cc = c - 2;
        float s = fb2[cc];
        for (int k = 0; k < 512; k++) s += g_hf[b*512+k] * fw2[k*18+cc];
        if      (cc < 3)  v = s*pos_std[cc]      + pos_mean[cc];
        else if (cc < 9)  v = s*rot_std[cc-3]    + rot_mean[cc-3];
        else if (cc < 12) v = s*pos_std[cc-9]    + pos_mean[cc-9];
        else              v = s*rot_std[cc-12]   + rot_mean[cc-12];
    }
    out[b*20+c] = v;
}

// ---------- launch ----------
extern "C" void kernel_launch(void* const* d_in, const int* in_sizes, int n_in,
                              void* d_out, int out_size)
{
    const float* in[31];
    if (in_sizes[0] == BATCH*NPTS*3) {
        for (int i = 0; i < 31; i++) in[i] = (const float*)d_in[i];
    } else {
        static const int a2s[31] = {2,4,6,8,10,12,14,16,18,24,26,23,25,
                                    20,22,19,21,0,27,28,29,30,
                                    1,3,5,7,9,11,13,15,17};
        for (int i = 0; i < 31; i++) in[a2s[i]] = (const float*)d_in[i];
    }
    const float* points = in[0];
    const float *w10=in[1],  *b10=in[2],  *w11=in[3],  *b11=in[4];
    const float *w12=in[5],  *b12=in[6],  *w20=in[7],  *b20=in[8];
    const float *w21=in[9],  *b21=in[10], *w22=in[11], *b22=in[12];
    const float *w30=in[13], *b30=in[14], *w31=in[15], *b31=in[16];
    const float *w32=in[17], *b32=in[18], *lw1=in[19], *lb1=in[20];
    const float *lw2=in[21], *lb2=in[22], *fw1=in[23], *fb1=in[24];
    const float *fw2=in[25], *fb2=in[26];
    const float *pos_mean=in[27], *pos_std=in[28];
    const float *rot_mean=in[29], *rot_std=in[30];
    float* out = (float*)d_out;

    fps1_kernel<<<BATCH, 256>>>(points);
    bq1_kernel<<<(BATCH*512)/4, 128>>>(points);
    d_sa1_l1<<<8192*32*64/256, 256>>>(points, w10, b10);
    k_sa1_l2<<<262144/256, 256>>>(w11, b11);     // 64->64   (256 rows/blk)
    k_sa1_l3<<<262144/128, 256>>>(w12, b12);     // 64->128  (128 rows/blk)
    d_sa1_pool<<<8192*128/256, 256>>>();
    fps2_kernel<<<BATCH, 256>>>();
    bq2_kernel<<<(BATCH*128)/4, 128>>>();
    gemm_sa2l1<<<131072/128, 256>>>(w20, b20);   // 131->128 (128 rows/blk)
    k_sa2_l2<<<131072/128, 256>>>(w21, b21);     // 128->128
    k_sa2_l3<<<131072/64, 256>>>(w22, b22);      // 128->256 (64 rows/blk)
    d_sa2_pool<<<2048*256/256, 256>>>();
    gemm_sa3l1<<<2048/64, 256>>>(w30, b30);      // 259->256 (64 rows/blk)
    k_sa3_l2<<<2048/32, 256>>>(w31, b31);        // 256->512 (32 rows/blk)
    k_sa3_l3<<<2048/16, 256>>>(w32, b32);        // 512->1024 (16 rows/blk)
    d_pool3<<<16*1024/256, 256>>>();
    d_head1<<<(16*768+255)/256, 256>>>(lw1, lb1, fw1, fb1);
    d_head2<<<1, 320>>>(lw2, lb2, fw2, fb2, pos_mean, pos_std, rot_mean, rot_std, out);
}

// round 17
// speedup vs baseline: 1.0744x; 1.0744x over previous
#include <cuda_runtime.h>
#include <math.h>

#define BATCH 16
#define NPTS  4096

// ---------- device scratch (16B-aligned for float4 access) ----------
__device__ __align__(16) float g_l1x[BATCH*512*3];
__device__ __align__(16) int   g_bq1[BATCH*512*32];
__device__ __align__(16) float g_l1f[BATCH*512*128];
__device__ __align__(16) float g_l2x[BATCH*128*3];
__device__ __align__(16) int   g_bq2[BATCH*128*64];
__device__ __align__(16) float g_l2f[BATCH*128*256];
__device__ __align__(16) float g_y1 [2048*256];
__device__ __align__(16) float g_y2 [2048*512];
__device__ __align__(16) float g_y3 [2048*1024];
__device__ __align__(16) float g_g  [BATCH*1024];
__device__ __align__(16) float g_hl [BATCH*256];
__device__ __align__(16) float g_hf [BATCH*512];
__device__ __align__(16) float g_ha [16777216];   // 64MB
__device__ __align__(16) float g_hb [16777216];   // 64MB
__device__ __align__(16) float g_hc [33554432];   // 128MB

// squared distance, exactly as XLA lowers sum((a-b)**2, -1)
__device__ __forceinline__ float dist2(float dx, float dy, float dz)
{
    return __fadd_rn(__fadd_rn(__fmul_rn(dx,dx), __fmul_rn(dy,dy)), __fmul_rn(dz,dz));
}

// ---------- farthest point sampling (register-resident) ----------
template<int N, int NP>
__device__ __forceinline__ void fps_body(const float* __restrict__ xyz,
                                         float* __restrict__ newxyz)
{
    constexpr int TPB = 256, NPER = N / TPB;
    __shared__ float rv[8];
    __shared__ int   ri[8];
    __shared__ int   s_far;
    __shared__ float sfx, sfy, sfz;
    const int b = blockIdx.x, t = threadIdx.x;
    const float* p = xyz + (size_t)b * N * 3;

    float lx[NPER], ly[NPER], lz[NPER], ld[NPER];
#pragma unroll
    for (int u = 0; u < NPER; u++) {
        int j = t + u*TPB;
        lx[u]=p[j*3]; ly[u]=p[j*3+1]; lz[u]=p[j*3+2]; ld[u]=1e10f;
    }
    if (t == 0) { sfx = lx[0]; sfy = ly[0]; sfz = lz[0]; }
    __syncthreads();

    for (int i = 0; i < NP; i++) {
        float fx = sfx, fy = sfy, fz = sfz;
        if (t == 0) {
            newxyz[((size_t)b*NP+i)*3+0]=fx;
            newxyz[((size_t)b*NP+i)*3+1]=fy;
            newxyz[((size_t)b*NP+i)*3+2]=fz;
        }
        float bv = -1.f; int bi = 0x7fffffff;
#pragma unroll
        for (int u = 0; u < NPER; u++) {
            float d  = dist2(lx[u]-fx, ly[u]-fy, lz[u]-fz);
            float nd = fminf(ld[u], d);
            ld[u] = nd;
            if (nd > bv) { bv = nd; bi = t + u*TPB; }
        }
#pragma unroll
        for (int off = 16; off; off >>= 1) {
            float ov = __shfl_down_sync(0xffffffffu, bv, off);
            int   oi = __shfl_down_sync(0xffffffffu, bi, off);
            if (ov > bv || (ov == bv && oi < bi)) { bv = ov; bi = oi; }
        }
        if ((t & 31) == 0) { rv[t>>5]=bv; ri[t>>5]=bi; }
        __syncthreads();
        if (t == 0) {
#pragma unroll
            for (int q = 1; q < 8; q++)
                if (rv[q] > bv || (rv[q] == bv && ri[q] < bi)) { bv=rv[q]; bi=ri[q]; }
            s_far = bi;
        }
        __syncthreads();
        int far = s_far;
        if (t == (far & (TPB-1))) {
            int u = far / TPB;
            sfx = lx[u]; sfy = ly[u]; sfz = lz[u];
        }
        __syncthreads();
    }
}
__global__ __launch_bounds__(256) void fps1_kernel(const float* __restrict__ pts)
{ fps_body<NPTS,512>(pts, g_l1x); }
__global__ __launch_bounds__(256) void fps2_kernel()
{ fps_body<512,128>(g_l1x, g_l2x); }

// ---------- ball query (warp per center) ----------
template<int NSRC, int NS>
__device__ __forceinline__ void bq_body(const float* __restrict__ xyz,
                                        const float* __restrict__ newxyz,
                                        int S, float r2, int* __restrict__ out)
{
    __shared__ int buf[4][NS];
    const int w = (blockIdx.x*blockDim.x + threadIdx.x) >> 5;
    const int lane = threadIdx.x & 31, wl = threadIdx.x >> 5;
    const int b = w / S;
    const float* p = xyz + (size_t)b * NSRC * 3;
    const float cx=newxyz[(size_t)w*3], cy=newxyz[(size_t)w*3+1], cz=newxyz[(size_t)w*3+2];
    int count = 0;
    for (int j0 = 0; j0 < NSRC && count < NS; j0 += 32) {
        int j = j0 + lane;
        float d = dist2(cx-p[j*3], cy-p[j*3+1], cz-p[j*3+2]);
        bool in = !(d > r2);
        unsigned m = __ballot_sync(0xffffffffu, in);
        int pos = count + __popc(m & ((1u<<lane)-1u));
        if (in && pos < NS) buf[wl][pos] = j;
        count += __popc(m);
    }
    __syncwarp();
    if (count > NS) count = NS;
    int first = buf[wl][0];
    for (int k = lane; k < NS; k += 32)
        out[(size_t)w*NS + k] = (k < count) ? buf[wl][k] : first;
}
__global__ __launch_bounds__(128) void bq1_kernel(const float* __restrict__ pts)
{ bq_body<NPTS,32>(pts, g_l1x, 512, (float)(0.2*0.2), g_bq1); }
__global__ __launch_bounds__(128) void bq2_kernel()
{ bq_body<512,64>(g_l1x, g_l2x, 128, (float)(0.4*0.4), g_bq2); }

// ======== smem-weight-staged 4x4 microtiled GEMM (64x64 output tile) ========
// Y[r,o] = relu(bias[o] + sum_k X[r,k] W[k,o]).
// Block: 256 threads = 16 row-groups x 16 col-groups, each thread 4x4 outputs.
// Weights staged in smem in 32-k slabs; activations read via L1 (broadcast).
// Per-output accumulation is k-ascending -> numerics identical to baseline.
template<int CIN, int COUT>
__device__ __forceinline__ void gemm_smem_body(const float* __restrict__ X,
    const float* __restrict__ W, const float* __restrict__ Bv,
    float* __restrict__ Y)
{
    __shared__ float Ws[32*64];
    const int t  = threadIdx.x;
    const int cg = t & 15;             // col group (0..15)
    const int rg = t >> 4;             // row group (0..15)
    const int colbase = blockIdx.y*64;
    const int oc = colbase + cg*4;
    const int r0 = blockIdx.x*64 + rg*4;
    const float* x0 = X + (size_t)r0*CIN;
    float4 bv4 = *reinterpret_cast<const float4*>(Bv + oc);
    float acc[4][4];
#pragma unroll
    for (int i = 0; i < 4; i++) {
        acc[i][0]=bv4.x; acc[i][1]=bv4.y; acc[i][2]=bv4.z; acc[i][3]=bv4.w;
    }
#pragma unroll 1
    for (int k0 = 0; k0 < CIN; k0 += 32) {
        __syncthreads();   // protect Ws from previous slab's readers
        // stage 32x64 weight slab: 512 float4s, 2 per thread
#pragma unroll
        for (int e = t; e < 512; e += 256) {
            int kk = e >> 4, c4 = (e & 15)*4;
            *reinterpret_cast<float4*>(Ws + kk*64 + c4) =
                *reinterpret_cast<const float4*>(W + (size_t)(k0+kk)*COUT + colbase + c4);
        }
        __syncthreads();
#pragma unroll
        for (int kc = 0; kc < 32; kc += 4) {
            float a[4][4];
#pragma unroll
            for (int i = 0; i < 4; i++) {
                float4 v = *reinterpret_cast<const float4*>(x0 + (size_t)i*CIN + k0 + kc);
                a[i][0]=v.x; a[i][1]=v.y; a[i][2]=v.z; a[i][3]=v.w;
            }
#pragma unroll
            for (int kk = 0; kk < 4; kk++) {
                float4 wv = *reinterpret_cast<const float4*>(Ws + (kc+kk)*64 + cg*4);
#pragma unroll
                for (int i = 0; i < 4; i++) {
                    acc[i][0] += a[i][kk]*wv.x;
                    acc[i][1] += a[i][kk]*wv.y;
                    acc[i][2] += a[i][kk]*wv.z;
                    acc[i][3] += a[i][kk]*wv.w;
                }
            }
        }
    }
#pragma unroll
    for (int i = 0; i < 4; i++) {
        float* yp = Y + (size_t)(r0+i)*COUT + oc;
        yp[0]=fmaxf(acc[i][0],0.f); yp[1]=fmaxf(acc[i][1],0.f);
        yp[2]=fmaxf(acc[i][2],0.f); yp[3]=fmaxf(acc[i][3],0.f);
    }
}

// per-layer wrappers (device globals named in device code only)
__global__ __launch_bounds__(256) void k_sa1_l2(const float* __restrict__ W, const float* __restrict__ B)
{ gemm_smem_body<64,64>(g_ha, W, B, g_hb); }
__global__ __launch_bounds__(256) void k_sa1_l3(const float* __restrict__ W, const float* __restrict__ B)
{ gemm_smem_body<64,128>(g_hb, W, B, g_hc); }
__global__ __launch_bounds__(256) void k_sa2_l2(const float* __restrict__ W, const float* __restrict__ B)
{ gemm_smem_body<128,128>(g_ha, W, B, g_hb); }
__global__ __launch_bounds__(256) void k_sa2_l3(const float* __restrict__ W, const float* __restrict__ B)
{ gemm_smem_body<128,256>(g_hb, W, B, g_hc); }
__global__ __launch_bounds__(256) void k_sa3_l2(const float* __restrict__ W, const float* __restrict__ B)
{ gemm_smem_body<256,512>(g_y1, W, B, g_y2); }
__global__ __launch_bounds__(256) void k_sa3_l3(const float* __restrict__ W, const float* __restrict__ B)
{ gemm_smem_body<512,1024>(g_y2, W, B, g_y3); }

// SA1 layer1 (3 -> 64), thread-per-output (tiny compute, memory bound)
__global__ void d_sa1_l1(const float* __restrict__ points,
                         const float* __restrict__ w, const float* __restrict__ bv)
{
    int i = blockIdx.x*blockDim.x + threadIdx.x;   // 8192*32*64
    int o = i & 63, r = (i>>6) & 31, g = i >> 11, b = g >> 9;
    int id = g_bq1[(size_t)g*32 + r];
    float acc = bv[o];
    for (int c = 0; c < 3; c++) {
        float x = points[((size_t)(b*NPTS)+id)*3 + c] - g_l1x[(size_t)g*3 + c];
        acc += x * w[c*64 + o];
    }
    g_ha[i] = fmaxf(acc, 0.f);
}
__global__ void d_sa1_pool()
{
    int i = blockIdx.x*blockDim.x + threadIdx.x;   // 8192*128
    int o = i & 127, g = i >> 7;
    float m = -1e30f;
    for (int r = 0; r < 32; r++)
        m = fmaxf(m, g_hc[((size_t)(g*32+r))*128 + o]);
    g_l1f[i] = m;
}

// SA2 layer1: gather + concat(xyz diff, 128 feats) -> 128, 4x4 microtiled (R15)
__global__ __launch_bounds__(256) void gemm_sa2l1(const float* __restrict__ W,
                                                  const float* __restrict__ Bv)
{
    constexpr int COUT = 128, TPR = COUT/4;   // 32
    const int t = threadIdx.x;
    const int o0 = (t % TPR)*4;
    const int r0 = blockIdx.x*32 + (t/TPR)*4;  // rows: 2048*64 = 131072
    float4 bv4 = *reinterpret_cast<const float4*>(Bv + o0);
    float4 w0 = *reinterpret_cast<const float4*>(W + 0*COUT + o0);
    float4 w1 = *reinterpret_cast<const float4*>(W + 1*COUT + o0);
    float4 w2 = *reinterpret_cast<const float4*>(W + 2*COUT + o0);
    const float* fp[4];
    float acc[4][4];
#pragma unroll
    for (int i = 0; i < 4; i++) {
        int r = r0 + i, g = r >> 6, rr = r & 63, b = g >> 7;
        int id = g_bq2[(size_t)g*64 + rr];
        float dx = g_l1x[(size_t)(b*512+id)*3+0] - g_l2x[(size_t)g*3+0];
        float dy = g_l1x[(size_t)(b*512+id)*3+1] - g_l2x[(size_t)g*3+1];
        float dz = g_l1x[(size_t)(b*512+id)*3+2] - g_l2x[(size_t)g*3+2];
        acc[i][0] = bv4.x + dx*w0.x + dy*w1.x + dz*w2.x;
        acc[i][1] = bv4.y + dx*w0.y + dy*w1.y + dz*w2.y;
        acc[i][2] = bv4.z + dx*w0.z + dy*w1.z + dz*w2.z;
        acc[i][3] = bv4.w + dx*w0.w + dy*w1.w + dz*w2.w;
        fp[i] = g_l1f + (size_t)(b*512+id)*128;
    }
#pragma unroll 2
    for (int k = 0; k < 128; k += 4) {
        float a[4][4];
#pragma unroll
        for (int i = 0; i < 4; i++) {
            float4 v = *reinterpret_cast<const float4*>(fp[i] + k);
            a[i][0]=v.x; a[i][1]=v.y; a[i][2]=v.z; a[i][3]=v.w;
        }
#pragma unroll
        for (int kk = 0; kk < 4; kk++) {
            float4 wv = *reinterpret_cast<const float4*>(W + (size_t)(3+k+kk)*COUT + o0);
#pragma unroll
            for (int i = 0; i < 4; i++) {
                acc[i][0] += a[i][kk]*wv.x;
                acc[i][1] += a[i][kk]*wv.y;
                acc[i][2] += a[i][kk]*wv.z;
                acc[i][3] += a[i][kk]*wv.w;
            }
        }
    }
#pragma unroll
    for (int i = 0; i < 4; i++) {
        float* yp = g_ha + (size_t)(r0+i)*COUT + o0;
        yp[0]=fmaxf(acc[i][0],0.f); yp[1]=fmaxf(acc[i][1],0.f);
        yp[2]=fmaxf(acc[i][2],0.f); yp[3]=fmaxf(acc[i][3],0.f);
    }
}
__global__ void d_sa2_pool()
{
    int i = blockIdx.x*blockDim.x + threadIdx.x;   // 2048*256
    int o = i & 255, g = i >> 8;
    float m = -1e30f;
    for (int r = 0; r < 64; r++)
        m = fmaxf(m, g_hc[((size_t)(g*64+r))*256 + o]);
    g_l2f[i] = m;
}

// SA3 layer1: concat(l2x, l2f) (3+256) -> 256, 4x4 microtiled (R15); rows = 2048
__global__ __launch_bounds__(256) void gemm_sa3l1(const float* __restrict__ W,
                                                  const float* __restrict__ Bv)
{
    constexpr int COUT = 256, TPR = COUT/4;   // 64
    const int t = threadIdx.x;
    const int o0 = (t % TPR)*4;
    const int r0 = blockIdx.x*16 + (t/TPR)*4;
    float4 bv4 = *reinterpret_cast<const float4*>(Bv + o0);
    float4 w0 = *reinterpret_cast<const float4*>(W + 0*COUT + o0);
    float4 w1 = *reinterpret_cast<const float4*>(W + 1*COUT + o0);
    float4 w2 = *reinterpret_cast<const float4*>(W + 2*COUT + o0);
    float acc[4][4];
#pragma unroll
    for (int i = 0; i < 4; i++) {
        int r = r0 + i;
        float x = g_l2x[(size_t)r*3+0], y = g_l2x[(size_t)r*3+1], z = g_l2x[(size_t)r*3+2];
        acc[i][0] = bv4.x + x*w0.x + y*w1.x + z*w2.x;
        acc[i][1] = bv4.y + x*w0.y + y*w1.y + z*w2.y;
        acc[i][2] = bv4.z + x*w0.z + y*w1.z + z*w2.z;
        acc[i][3] = bv4.w + x*w0.w + y*w1.w + z*w2.w;
    }
    const float* x0 = g_l2f + (size_t)r0*256;
#pragma unroll 2
    for (int k = 0; k < 256; k += 4) {
        float a[4][4];
#pragma unroll
        for (int i = 0; i < 4; i++) {
            float4 v = *reinterpret_cast<const float4*>(x0 + (size_t)i*256 + k);
            a[i][0]=v.x; a[i][1]=v.y; a[i][2]=v.z; a[i][3]=v.w;
        }
#pragma unroll
        for (int kk = 0; kk < 4; kk++) {
            float4 wv = *reinterpret_cast<const float4*>(W + (size_t)(3+k+kk)*COUT + o0);
#pragma unroll
            for (int i = 0; i < 4; i++) {
                acc[i][0] += a[i][kk]*wv.x;
                acc[i][1] += a[i][kk]*wv.y;
                acc[i][2] += a[i][kk]*wv.z;
                acc[i][3] += a[i][kk]*wv.w;
            }
        }
    }
#pragma unroll
    for (int i = 0; i < 4; i++) {
        float* yp = g_y1 + (size_t)(r0+i)*COUT + o0;
        yp[0]=fmaxf(acc[i][0],0.f); yp[1]=fmaxf(acc[i][1],0.f);
        yp[2]=fmaxf(acc[i][2],0.f); yp[3]=fmaxf(acc[i][3],0.f);
    }
}
__global__ void d_pool3()
{
    int i = blockIdx.x*blockDim.x + threadIdx.x;   // 16*1024
    int b = i >> 10, c = i & 1023;
    float m = -1e30f;
    for (int r = 0; r < 128; r++)
        m = fmaxf(m, g_y3[(size_t)((b*128+r)<<10) + c]);
    g_g[i] = m;
}
// heads
__global__ void d_head1(const float* __restrict__ lw1, const float* __restrict__ lb1,
                        const float* __restrict__ fw1, const float* __restrict__ fb1)
{
    int i = blockIdx.x*blockDim.x + threadIdx.x;   // 16*768
    if (i >= 16*768) return;
    int b = i / 768, o = i % 768;
    if (o < 256) {
        float s = lb1[o];
        for (int k = 0; k < 1024; k++) s += g_g[(size_t)b*1024+k] * lw1[(size_t)k*256 + o];
        g_hl[b*256+o] = fmaxf(s, 0.f);
    } else {
        int o2 = o - 256;
        float s = fb1[o2];
        for (int k = 0; k < 1024; k++) s += g_g[(size_t)b*1024+k] * fw1[(size_t)k*512 + o2];
        g_hf[b*512+o2] = fmaxf(s, 0.f);
    }
}
__global__ void d_head2(const float* __restrict__ lw2, const float* __restrict__ lb2,
                        const float* __restrict__ fw2, const float* __restrict__ fb2,
                        const float* __restrict__ pos_mean, const float* __restrict__ pos_std,
                        const float* __restrict__ rot_mean, const float* __restrict__ rot_std,
                        float* __restrict__ out)
{
    int i = threadIdx.x;
    if (i >= 320) return;
    int b = i / 20, c = i % 20;
    float v;
    if (c < 2) {
        float s = lb2[c];
        for (int k = 0; k < 256; k++) s += g_hl[b*256+k] * lw2[k*2+c];
        v = 1.f/(1.f + expf(-s));
    } else {
        int cc = c - 2;
        float s = fb2[cc];
        for (int k = 0; k < 512; k++) s += g_hf[b*512+k] * fw2[k*18+cc];
        if      (cc < 3)  v = s*pos_std[cc]      + pos_mean[cc];
        else if (cc < 9)  v = s*rot_std[cc-3]    + rot_mean[cc-3];
        else if (cc < 12) v = s*pos_std[cc-9]    + pos_mean[cc-9];
        else              v = s*rot_std[cc-12]   + rot_mean[cc-12];
    }
    out[b*20+c] = v;
}

// ---------- launch ----------
extern "C" void kernel_launch(void* const* d_in, const int* in_sizes, int n_in,
                              void* d_out, int out_size)
{
    const float* in[31];
    if (in_sizes[0] == BATCH*NPTS*3) {
        for (int i = 0; i < 31; i++) in[i] = (const float*)d_in[i];
    } else {
        static const int a2s[31] = {2,4,6,8,10,12,14,16,18,24,26,23,25,
                                    20,22,19,21,0,27,28,29,30,
                                    1,3,5,7,9,11,13,15,17};
        for (int i = 0; i < 31; i++) in[a2s[i]] = (const float*)d_in[i];
    }
    const float* points = in[0];
    const float *w10=in[1],  *b10=in[2],  *w11=in[3],  *b11=in[4];
    const float *w12=in[5],  *b12=in[6],  *w20=in[7],  *b20=in[8];
    const float *w21=in[9],  *b21=in[10], *w22=in[11], *b22=in[12];
    const float *w30=in[13], *b30=in[14], *w31=in[15], *b31=in[16];
    const float *w32=in[17], *b32=in[18], *lw1=in[19], *lb1=in[20];
    const float *lw2=in[21], *lb2=in[22], *fw1=in[23], *fb1=in[24];
    const float *fw2=in[25], *fb2=in[26];
    const float *pos_mean=in[27], *pos_std=in[28];
    const float *rot_mean=in[29], *rot_std=in[30];
    float* out = (float*)d_out;

    fps1_kernel<<<BATCH, 256>>>(points);
    bq1_kernel<<<(BATCH*512)/4, 128>>>(points);
    d_sa1_l1<<<8192*32*64/256, 256>>>(points, w10, b10);
    k_sa1_l2<<<dim3(4096,1), 256>>>(w11, b11);     // 64->64
    k_sa1_l3<<<dim3(4096,2), 256>>>(w12, b12);     // 64->128
    d_sa1_pool<<<8192*128/256, 256>>>();
    fps2_kernel<<<BATCH, 256>>>();
    bq2_kernel<<<(BATCH*128)/4, 128>>>();
    gemm_sa2l1<<<131072/32, 256>>>(w20, b20);      // 131->128
    k_sa2_l2<<<dim3(2048,2), 256>>>(w21, b21);     // 128->128
    k_sa2_l3<<<dim3(2048,4), 256>>>(w22, b22);     // 128->256
    d_sa2_pool<<<2048*256/256, 256>>>();
    gemm_sa3l1<<<2048/16, 256>>>(w30, b30);        // 259->256
    k_sa3_l2<<<dim3(32,8), 256>>>(w31, b31);       // 256->512
    k_sa3_l3<<<dim3(32,16), 256>>>(w32, b32);      // 512->1024
    d_pool3<<<16*1024/256, 256>>>();
    d_head1<<<(16*768+255)/256, 256>>>(lw1, lb1, fw1, fb1);
    d_head2<<<1, 320>>>(lw2, lb2, fw2, fb2, pos_mean, pos_std, rot_mean, rot_std, out);
}